// round 15
// baseline (speedup 1.0000x reference)
#include <cuda_runtime.h>
#include <cuda_bf16.h>

#define N_NODES 50000
#define F1 32
#define F2 16
#define EPT 4          // edges/thread: count kernel
#define SEPT 8         // edges/thread: scatter kernel
#define T 256
#define MAXE 4400000   // capacity of sorted edge array (actual = 4.2M)

// ---------------- scratch (device globals; no allocation allowed) ----------
__device__ int   g_cnt_out[3][N_NODES];
__device__ int   g_cnt_in [3][N_NODES];
__device__ int   g_off[3][N_NODES];                        // CSR segment start (absolute)
__device__ int   g_cur[3][N_NODES];                        // scatter cursors
__device__ int   g_esrc[MAXE];                             // src ids sorted by (r, dst)
__device__ __align__(16) unsigned int g_h1b[3][N_NODES * (F2 / 2)]; // h1 packed bf16x2
__device__ __align__(16) float g_m [3][N_NODES * F2];      // fp32 raw aggregates
__device__ float g_s   [3][N_NODES];                       // layer-2 scalar projections
__device__ float g_out3[3][N_NODES];

__device__ __forceinline__ float rinv_of(int c) {
    return rsqrtf(fmaxf((float)c, 1.0f));
}
__device__ __forceinline__ unsigned int pack_bf2(float a, float b) {
    __nv_bfloat162 h = __float22bfloat162_rn(make_float2(a, b));
    return *reinterpret_cast<unsigned int*>(&h);
}
__device__ __forceinline__ void acc_bf16x8(float* a, uint4 v) {
    float2 f;
    f = __bfloat1622float2(*reinterpret_cast<__nv_bfloat162*>(&v.x)); a[0] += f.x; a[1] += f.y;
    f = __bfloat1622float2(*reinterpret_cast<__nv_bfloat162*>(&v.y)); a[2] += f.x; a[3] += f.y;
    f = __bfloat1622float2(*reinterpret_cast<__nv_bfloat162*>(&v.z)); a[4] += f.x; a[5] += f.y;
    f = __bfloat1622float2(*reinterpret_cast<__nv_bfloat162*>(&v.w)); a[6] += f.x; a[7] += f.y;
}

struct RelSel { const int* s; const int* d; int E; int r; int b; };
__device__ __forceinline__ RelSel pick_rel(
    int b, const int* s0, const int* d0, int E0, int B0,
    const int* s1, const int* d1, int E1, int B1,
    const int* s2, const int* d2, int E2) {
    RelSel rs;
    if (b < B0)            { rs = {s0, d0, E0, 0, b}; }
    else if (b < B0 + B1)  { rs = {s1, d1, E1, 1, b - B0}; }
    else                   { rs = {s2, d2, E2, 2, b - B0 - B1}; }
    return rs;
}

// ---------------- K1: zero degree counters ---------------------------------
__global__ void k_zero() {
    int i = blockIdx.x * blockDim.x + threadIdx.x;
    const int nd = 3 * N_NODES;
    if (i < nd) {
        ((int*)g_cnt_out)[i] = 0;
        ((int*)g_cnt_in)[i]  = 0;
    }
}

// ---------------- K2: fused degree counting --------------------------------
__global__ void k_count_all(const int* __restrict__ s0, const int* __restrict__ d0, int E0, int B0,
                            const int* __restrict__ s1, const int* __restrict__ d1, int E1, int B1,
                            const int* __restrict__ s2, const int* __restrict__ d2, int E2) {
    RelSel rs = pick_rel(blockIdx.x, s0, d0, E0, B0, s1, d1, E1, B1, s2, d2, E2);
    int i0 = (rs.b * T + threadIdx.x) * EPT;
    int* co = &g_cnt_out[rs.r][0];
    int* ci = &g_cnt_in [rs.r][0];
    if (i0 + EPT <= rs.E) {
        int4 sv = *(const int4*)(rs.s + i0);
        int4 dv = *(const int4*)(rs.d + i0);
        atomicAdd(co + sv.x, 1); atomicAdd(co + sv.y, 1);
        atomicAdd(co + sv.z, 1); atomicAdd(co + sv.w, 1);
        atomicAdd(ci + dv.x, 1); atomicAdd(ci + dv.y, 1);
        atomicAdd(ci + dv.z, 1); atomicAdd(ci + dv.w, 1);
    } else {
        for (int i = i0; i < rs.E; i++) {
            atomicAdd(co + rs.s[i], 1);
            atomicAdd(ci + rs.d[i], 1);
        }
    }
}

// ---------------- K3: per-relation exclusive scan of in-degrees ------------
__global__ void k_scan(int base0, int base1, int base2) {
    const int BT = 1024;
    __shared__ int sm[BT];
    int r = blockIdx.x;
    int base = (r == 0) ? base0 : (r == 1) ? base1 : base2;
    const int CH = (N_NODES + BT - 1) / BT;
    int t = threadIdx.x;
    int lo = t * CH;
    int hi = min(lo + CH, N_NODES);

    int sum = 0;
    for (int i = lo; i < hi; i++) sum += g_cnt_in[r][i];
    sm[t] = sum;
    __syncthreads();
    for (int off = 1; off < BT; off <<= 1) {
        int y = (t >= off) ? sm[t - off] : 0;
        __syncthreads();
        sm[t] += y;
        __syncthreads();
    }
    int run = base + sm[t] - sum;   // exclusive prefix
    for (int i = lo; i < hi; i++) {
        g_off[r][i] = run;
        g_cur[r][i] = run;
        run += g_cnt_in[r][i];
    }
}

// ---------------- K4: scatter edges into CSR (EPT=8 for MLP) ---------------
__global__ void k_scatter_all(const int* __restrict__ s0, const int* __restrict__ d0, int E0, int B0,
                              const int* __restrict__ s1, const int* __restrict__ d1, int E1, int B1,
                              const int* __restrict__ s2, const int* __restrict__ d2, int E2) {
    RelSel rs = pick_rel(blockIdx.x, s0, d0, E0, B0, s1, d1, E1, B1, s2, d2, E2);
    int i0 = (rs.b * T + threadIdx.x) * SEPT;
    int* cur = &g_cur[rs.r][0];
    if (i0 + SEPT <= rs.E) {
        int4 sa = *(const int4*)(rs.s + i0);
        int4 sb = *(const int4*)(rs.s + i0 + 4);
        int4 da = *(const int4*)(rs.d + i0);
        int4 db = *(const int4*)(rs.d + i0 + 4);
        int p0 = atomicAdd(cur + da.x, 1);
        int p1 = atomicAdd(cur + da.y, 1);
        int p2 = atomicAdd(cur + da.z, 1);
        int p3 = atomicAdd(cur + da.w, 1);
        int p4 = atomicAdd(cur + db.x, 1);
        int p5 = atomicAdd(cur + db.y, 1);
        int p6 = atomicAdd(cur + db.z, 1);
        int p7 = atomicAdd(cur + db.w, 1);
        g_esrc[p0] = sa.x; g_esrc[p1] = sa.y; g_esrc[p2] = sa.z; g_esrc[p3] = sa.w;
        g_esrc[p4] = sb.x; g_esrc[p5] = sb.y; g_esrc[p6] = sb.z; g_esrc[p7] = sb.w;
    } else {
        for (int i = i0; i < rs.E; i++) {
            int p = atomicAdd(cur + rs.d[i], 1);
            g_esrc[p] = rs.s[i];
        }
    }
}

// ---------------- K5: h1_r[n] = (x[n]*rinv_out_r[n]) @ W1[r], bf16-packed --
__global__ void k_h1(const float* __restrict__ x, const float* __restrict__ W1) {
    __shared__ float sW[3 * F1 * F2];
    for (int t = threadIdx.x; t < 3 * F1 * F2; t += blockDim.x) sW[t] = W1[t];
    __syncthreads();
    int n = blockIdx.x * blockDim.x + threadIdx.x;
    if (n >= N_NODES) return;

    float xr[F1];
    const float4* xp = (const float4*)(x + (size_t)n * F1);
#pragma unroll
    for (int k = 0; k < F1 / 4; k++) {
        float4 v = xp[k];
        xr[4 * k + 0] = v.x; xr[4 * k + 1] = v.y;
        xr[4 * k + 2] = v.z; xr[4 * k + 3] = v.w;
    }
#pragma unroll
    for (int r = 0; r < 3; r++) {
        float scale = rinv_of(g_cnt_out[r][n]);
        float acc[F2];
#pragma unroll
        for (int j = 0; j < F2; j++) acc[j] = 0.0f;
        const float* wr = sW + r * F1 * F2;
#pragma unroll
        for (int i = 0; i < F1; i++) {
            float xv = xr[i];
#pragma unroll
            for (int j = 0; j < F2; j++) acc[j] = fmaf(xv, wr[i * F2 + j], acc[j]);
        }
        uint4 w0, w1;
        w0.x = pack_bf2(acc[0] * scale,  acc[1] * scale);
        w0.y = pack_bf2(acc[2] * scale,  acc[3] * scale);
        w0.z = pack_bf2(acc[4] * scale,  acc[5] * scale);
        w0.w = pack_bf2(acc[6] * scale,  acc[7] * scale);
        w1.x = pack_bf2(acc[8] * scale,  acc[9] * scale);
        w1.y = pack_bf2(acc[10] * scale, acc[11] * scale);
        w1.z = pack_bf2(acc[12] * scale, acc[13] * scale);
        w1.w = pack_bf2(acc[14] * scale, acc[15] * scale);
        uint4* op = (uint4*)&g_h1b[r][(size_t)n * (F2 / 2)];
        op[0] = w0;
        op[1] = w1;
    }
}

// ---------------- K6: atomic-free layer-1 gather (bf16 messages) -----------
// thread = (r, dst, chunk of 8 dims): 3*N*2 threads.
__global__ void k_gather1() {
    int tid = blockIdx.x * blockDim.x + threadIdx.x;
    int chunk = tid & 1;
    int idx = tid >> 1;
    if (idx >= 3 * N_NODES) return;
    int r = idx / N_NODES;
    int n = idx - r * N_NODES;

    int start = g_off[r][n];
    int cnt   = g_cnt_in[r][n];
    const int* ep = g_esrc + start;
    const uint4* h1 = (const uint4*)&g_h1b[r][0];

    float a0[8] = {0.f, 0.f, 0.f, 0.f, 0.f, 0.f, 0.f, 0.f};
    float a1[8] = {0.f, 0.f, 0.f, 0.f, 0.f, 0.f, 0.f, 0.f};
    int e = 0;
    for (; e + 2 <= cnt; e += 2) {
        int s0 = ep[e], s1 = ep[e + 1];
        uint4 v0 = h1[(size_t)s0 * 2 + chunk];
        uint4 v1 = h1[(size_t)s1 * 2 + chunk];
        acc_bf16x8(a0, v0);
        acc_bf16x8(a1, v1);
    }
    if (e < cnt) {
        uint4 v0 = h1[(size_t)ep[e] * 2 + chunk];
        acc_bf16x8(a0, v0);
    }
#pragma unroll
    for (int j = 0; j < 8; j++) a0[j] += a1[j];
    float4* mp = (float4*)&g_m[r][(size_t)n * F2 + chunk * 8];
    mp[0] = make_float4(a0[0], a0[1], a0[2], a0[3]);
    mp[1] = make_float4(a0[4], a0[5], a0[6], a0[7]);
}

// ---------------- K7: finish layer 1, project layer 2 ----------------------
__global__ void k_l2prep(const float* __restrict__ b1, const float* __restrict__ W2) {
    __shared__ float sb1[F2];
    __shared__ float sW2[3][F2];
    if (threadIdx.x < F2)
        sb1[threadIdx.x] = b1[threadIdx.x] + b1[F2 + threadIdx.x] + b1[2 * F2 + threadIdx.x];
    if (threadIdx.x < 3 * F2)
        sW2[threadIdx.x / F2][threadIdx.x % F2] = W2[threadIdx.x];
    __syncthreads();

    int n = blockIdx.x * blockDim.x + threadIdx.x;
    if (n >= N_NODES) return;

    float h[F2];
#pragma unroll
    for (int j = 0; j < F2; j++) h[j] = sb1[j];
#pragma unroll
    for (int r = 0; r < 3; r++) {
        float ri = rinv_of(g_cnt_in[r][n]);
        const float4* mp = (const float4*)&g_m[r][(size_t)n * F2];
#pragma unroll
        for (int k = 0; k < F2 / 4; k++) {
            float4 v = mp[k];
            h[4 * k + 0] = fmaf(v.x, ri, h[4 * k + 0]);
            h[4 * k + 1] = fmaf(v.y, ri, h[4 * k + 1]);
            h[4 * k + 2] = fmaf(v.z, ri, h[4 * k + 2]);
            h[4 * k + 3] = fmaf(v.w, ri, h[4 * k + 3]);
        }
    }
#pragma unroll
    for (int j = 0; j < F2; j++) h[j] = fmaxf(h[j], 0.0f);

#pragma unroll
    for (int r = 0; r < 3; r++) {
        float dot = 0.0f;
#pragma unroll
        for (int j = 0; j < F2; j++) dot = fmaf(h[j], sW2[r][j], dot);
        g_s[r][n] = dot * rinv_of(g_cnt_out[r][n]);
    }
}

// ---------------- K8: atomic-free layer-2 gather ---------------------------
__global__ void k_gather2() {
    int idx = blockIdx.x * blockDim.x + threadIdx.x;
    if (idx >= 3 * N_NODES) return;
    int r = idx / N_NODES;
    int n = idx - r * N_NODES;

    int start = g_off[r][n];
    int cnt   = g_cnt_in[r][n];
    const int* ep = g_esrc + start;
    const float* sc = &g_s[r][0];

    float a = 0.0f, b = 0.0f, c = 0.0f, d = 0.0f;
    int e = 0;
    for (; e + 4 <= cnt; e += 4) {
        a += sc[ep[e]];
        b += sc[ep[e + 1]];
        c += sc[ep[e + 2]];
        d += sc[ep[e + 3]];
    }
    for (; e < cnt; e++) a += sc[ep[e]];
    g_out3[r][n] = (a + b) + (c + d);
}

// ---------------- K9: final: scale + bias + store to d_out -----------------
__global__ void k_final(const float* __restrict__ b2, float* __restrict__ out) {
    __shared__ float sb2sum;
    if (threadIdx.x == 0) sb2sum = b2[0] + b2[1] + b2[2];
    __syncthreads();
    int n = blockIdx.x * blockDim.x + threadIdx.x;
    if (n >= N_NODES) return;
    float v = sb2sum;
#pragma unroll
    for (int r = 0; r < 3; r++)
        v = fmaf(g_out3[r][n], rinv_of(g_cnt_in[r][n]), v);
    out[n] = v;
}

// ---------------- launch ----------------------------------------------------
extern "C" void kernel_launch(void* const* d_in, const int* in_sizes, int n_in,
                              void* d_out, int out_size) {
    const float* x = (const float*)d_in[0];
    const int* s0 = (const int*)d_in[1]; const int* d0 = (const int*)d_in[2];
    const int* s1 = (const int*)d_in[3]; const int* d1 = (const int*)d_in[4];
    const int* s2 = (const int*)d_in[5]; const int* d2 = (const int*)d_in[6];
    int E0 = in_sizes[1], E1 = in_sizes[3], E2 = in_sizes[5];
    const float* W1 = (const float*)d_in[7];
    const float* b1 = (const float*)d_in[8];
    const float* W2 = (const float*)d_in[9];
    const float* b2 = (const float*)d_in[10];
    float* out = (float*)d_out;

    const int CPB = T * EPT;    // count blocks
    int C0 = (E0 + CPB - 1) / CPB;
    int C1 = (E1 + CPB - 1) / CPB;
    int C2 = (E2 + CPB - 1) / CPB;
    const int SPB = T * SEPT;   // scatter blocks
    int S0 = (E0 + SPB - 1) / SPB;
    int S1 = (E1 + SPB - 1) / SPB;
    int S2 = (E2 + SPB - 1) / SPB;

    k_zero<<<(3 * N_NODES + T - 1) / T, T>>>();
    k_count_all<<<C0 + C1 + C2, T>>>(s0, d0, E0, C0, s1, d1, E1, C1, s2, d2, E2);
    k_scan<<<3, 1024>>>(0, E0, E0 + E1);
    k_scatter_all<<<S0 + S1 + S2, T>>>(s0, d0, E0, S0, s1, d1, E1, S1, s2, d2, E2);
    k_h1<<<(N_NODES + T - 1) / T, T>>>(x, W1);
    k_gather1<<<(3 * N_NODES * 2 + T - 1) / T, T>>>();
    k_l2prep<<<(N_NODES + T - 1) / T, T>>>(b1, W2);
    k_gather2<<<(3 * N_NODES + T - 1) / T, T>>>();
    k_final<<<(N_NODES + T - 1) / T, T>>>(b2, out);
}